// round 12
// baseline (speedup 1.0000x reference)
#include <cuda_runtime.h>
#include <stdlib.h>

#define Bg 256
#define Nn 512
#define Fd 128
#define Eg 2097152
#define Kp1 256
#define Kp2 128
#define BN (Bg*Nn)
#define NEG_SLOPE 0.2f
#define LAMBW 1.0f

// Only ctor: set EAGER module loading before any CUDA use. NO CUDA calls
// pre-main — runtime init must happen AFTER fatbin registration (inverting
// that order is what made R7-R10 launches fail: delta=0 + 0 captured nodes).
__attribute__((constructor))
static void hx_env(){ setenv("CUDA_MODULE_LOADING", "EAGER", 1); }

// ------------------- scratch: one aliased pool + small arrays -------------------
// Liveness-checked layout (float offsets), with in-place GEMMs (X==O safe:
// each block reads only its own 64 rows, all reads precede its writes):
//  P1 [0,16777216):          xagg -> h (in-place x@W1) -> A1
//  P2 [16777216,25165824):   hk -> hw (in-place hk@W2) -> smooth -> h2k|A2
//  P3 [25165824,33554432):   h2 -> h3
#define OFF_XAGG 0
#define OFF_H    0
#define OFF_A1   0
#define OFF_HK   16777216
#define OFF_HW   16777216
#define OFF_H2   25165824
#define OFF_H2K  16777216
#define OFF_A2   20971520
#define OFF_H3   25165824
#define POOL_FLOATS 33554432
__device__ __align__(16) float d_pool[POOL_FLOATS];

__device__ int   d_deg[BN];
__device__ float d_dinv1[BN];       // rsqrt(deg+1)
__device__ float d_dinv0[BN];       // deg>0 ? rsqrt(deg) : 0
__device__ int   d_rowptr[BN+1];
__device__ int   d_cursor[BN];
__device__ int   d_csrsrc[Eg];
__device__ int   d_blocksum[BN/256];
__device__ float d_score[BN];
__device__ int   d_idx1[Bg*Kp1];
__device__ int   d_pos1[BN];
__device__ float d_q1[Bg*Kp1];
__device__ float d_s1v[Bg*Kp1];
__device__ float d_dinvA[Bg*Kp1];
__device__ float d_dinvB[Bg*Kp1];
__device__ int   d_idx2[Bg*Kp2];
__device__ float d_q2[Bg*Kp2];
__device__ float d_s2v[Bg*Kp2];

__device__ __forceinline__ float neg_inf(){ return __int_as_float(0xff800000); }

// ------------------- small utility kernels (all blocks <= 256 threads) -------------------
__global__ void k_zero_deg(){
    int i = blockIdx.x*blockDim.x + threadIdx.x;
    if (i < BN) d_deg[i] = 0;
}
__global__ void k_zero_pool(int off, int n){
    float* p = d_pool + off;
    for (int i = blockIdx.x*blockDim.x + threadIdx.x; i < n; i += gridDim.x*blockDim.x)
        p[i] = 0.f;
}
__global__ void k_degree(const int* __restrict__ dst){
    int e = blockIdx.x*blockDim.x + threadIdx.x;
    if (e < Eg) atomicAdd(&d_deg[dst[e]], 1);
}
__global__ void k_dinv(){
    int i = blockIdx.x*blockDim.x + threadIdx.x;
    if (i >= BN) return;
    int dg = d_deg[i];
    d_dinv1[i] = rsqrtf((float)dg + 1.0f);
    d_dinv0[i] = dg > 0 ? rsqrtf((float)dg) : 0.f;
}
// ---- 3-kernel exclusive scan of d_deg -> d_rowptr (256-elem blocks) ----
__global__ void k_scan1(){
    __shared__ int s[256];
    int i = blockIdx.x*256 + threadIdx.x;
    int v = d_deg[i];
    s[threadIdx.x] = v;
    __syncthreads();
    for (int off = 1; off < 256; off <<= 1){
        int t = (threadIdx.x >= off) ? s[threadIdx.x - off] : 0;
        __syncthreads();
        s[threadIdx.x] += t;
        __syncthreads();
    }
    d_rowptr[i] = s[threadIdx.x] - v;
    if (threadIdx.x == 255) d_blocksum[blockIdx.x] = s[255];
}
__global__ void k_scan2(){
    if (threadIdx.x == 0){
        int acc = 0;
        for (int i = 0; i < BN/256; i++){
            int v = d_blocksum[i];
            d_blocksum[i] = acc;
            acc += v;
        }
    }
}
__global__ void k_scan3(){
    int i = blockIdx.x*256 + threadIdx.x;
    int rp = d_rowptr[i] + d_blocksum[blockIdx.x];
    d_rowptr[i] = rp;
    d_cursor[i] = rp;
    if (i == 0) d_rowptr[BN] = Eg;
}
__global__ void k_fill(const int* __restrict__ src, const int* __restrict__ dst){
    int e = blockIdx.x*blockDim.x + threadIdx.x;
    if (e >= Eg) return;
    int p = atomicAdd(&d_cursor[dst[e]], 1);
    d_csrsrc[p] = src[e];
}

// ------------------- normalized aggregation of raw x (warp per node) -------------------
__global__ void k_aggx(const float* __restrict__ x, int oXagg){
    float* xagg = d_pool + oXagg;
    int node = (blockIdx.x*blockDim.x + threadIdx.x) >> 5;
    int lane = threadIdx.x & 31;
    if (node >= BN) return;
    float di = d_dinv1[node];
    int beg = d_rowptr[node], end = d_rowptr[node+1];
    float a0=0,a1=0,a2=0,a3=0;
    for (int e = beg; e < end; e++){
        int s = d_csrsrc[e];
        float c = d_dinv1[s] * di;
        const float* xr = &x[(size_t)s*128];
        a0 += xr[lane]*c; a1 += xr[lane+32]*c; a2 += xr[lane+64]*c; a3 += xr[lane+96]*c;
    }
    const float* xs = &x[(size_t)node*128];
    float sc = di*di;
    a0 += xs[lane]*sc;    a1 += xs[lane+32]*sc;
    a2 += xs[lane+64]*sc; a3 += xs[lane+96]*sc;
    float* o = &xagg[(size_t)node*128];
    o[lane] = a0; o[lane+32] = a1; o[lane+64] = a2; o[lane+96] = a3;
}

// ------------------- GEMM: pool[oO] = act(pool[oX] @ W + bias); oX==oO allowed -------------------
__global__ __launch_bounds__(256) void k_gemm(int oX, const float* __restrict__ W,
                                              int oO, int M,
                                              const float* __restrict__ bias,
                                              int doRelu){
    const float* X = d_pool + oX;
    float* O = d_pool + oO;
    __shared__ float Xs[64][32];
    __shared__ float Ws[32][128];
    int ty = threadIdx.x >> 5, tx = threadIdx.x & 31;
    int row0 = blockIdx.x * 64;
    float acc[8][4];
    #pragma unroll
    for (int r = 0; r < 8; r++){ acc[r][0]=acc[r][1]=acc[r][2]=acc[r][3]=0.f; }
    for (int kb = 0; kb < 128; kb += 32){
        #pragma unroll
        for (int t = 0; t < 8; t++){
            int e = threadIdx.x + 256*t; int i = e >> 5, k = e & 31;
            Xs[i][k] = X[(size_t)(row0+i)*128 + kb + k];
        }
        #pragma unroll
        for (int t = 0; t < 16; t++){
            int e = threadIdx.x + 256*t; int kk = e >> 7, c = e & 127;
            Ws[kk][c] = W[(kb+kk)*128 + c];
        }
        __syncthreads();
        #pragma unroll
        for (int k = 0; k < 32; k++){
            float4 wv = *reinterpret_cast<const float4*>(&Ws[k][tx*4]);
            #pragma unroll
            for (int r = 0; r < 8; r++){
                float xv = Xs[ty*8 + r][k];
                acc[r][0] += xv*wv.x; acc[r][1] += xv*wv.y;
                acc[r][2] += xv*wv.z; acc[r][3] += xv*wv.w;
            }
        }
        __syncthreads();
    }
    float4 bv = make_float4(0.f,0.f,0.f,0.f);
    if (bias) bv = *reinterpret_cast<const float4*>(&bias[tx*4]);
    #pragma unroll
    for (int r = 0; r < 8; r++){
        float v0 = acc[r][0]+bv.x, v1 = acc[r][1]+bv.y, v2 = acc[r][2]+bv.z, v3 = acc[r][3]+bv.w;
        if (doRelu){ v0=fmaxf(v0,0.f); v1=fmaxf(v1,0.f); v2=fmaxf(v2,0.f); v3=fmaxf(v3,0.f); }
        float4 v = make_float4(v0,v1,v2,v3);
        *reinterpret_cast<float4*>(&O[(size_t)(row0+ty*8+r)*128 + tx*4]) = v;
    }
}

// ------------------- info-score (edge, on pool[oH]); writes d_score -------------------
__global__ void k_info1(int oH){
    const float* h = d_pool + oH;
    int node = (blockIdx.x*blockDim.x + threadIdx.x) >> 5;
    int lane = threadIdx.x & 31;
    if (node >= BN) return;
    float di = d_dinv0[node];
    int beg = d_rowptr[node], end = d_rowptr[node+1];
    float a0=0,a1=0,a2=0,a3=0;
    for (int e = beg; e < end; e++){
        int s = d_csrsrc[e];
        float c = d_dinv0[s] * di;
        const float* hr = &h[(size_t)s*128];
        a0 += hr[lane]*c; a1 += hr[lane+32]*c; a2 += hr[lane+64]*c; a3 += hr[lane+96]*c;
    }
    const float* hs = &h[(size_t)node*128];
    float sum = fabsf(hs[lane]-a0) + fabsf(hs[lane+32]-a1)
              + fabsf(hs[lane+64]-a2) + fabsf(hs[lane+96]-a3);
    for (int o = 16; o > 0; o >>= 1) sum += __shfl_xor_sync(0xffffffffu, sum, o);
    if (lane == 0) d_score[node] = sum;
}

// ------------------- top-256-of-512 (bitonic, 256 threads x 2 elems) -------------------
__global__ void k_topk512(){
    __shared__ float v[512];
    __shared__ int   id[512];
    int g = blockIdx.x, t = threadIdx.x;
    v[t]       = d_score[g*512 + t];       id[t]       = t;
    v[t + 256] = d_score[g*512 + t + 256]; id[t + 256] = t + 256;
    __syncthreads();
    for (int k = 2; k <= 512; k <<= 1){
        for (int j = k >> 1; j > 0; j >>= 1){
            #pragma unroll
            for (int half = 0; half < 2; half++){
                int i = t + half*256;
                int ixj = i ^ j;
                if (ixj > i){
                    float va = v[i], vb = v[ixj]; int ia = id[i], ib = id[ixj];
                    bool aFirst = (va > vb) || (va == vb && ia < ib);
                    bool want = ((i & k) == 0);
                    if (aFirst != want){ v[i]=vb; v[ixj]=va; id[i]=ib; id[ixj]=ia; }
                }
            }
            __syncthreads();
        }
    }
    d_pos1[g*512 + t] = -1;
    d_pos1[g*512 + t + 256] = -1;
    __syncthreads();
    d_idx1[g*256 + t] = id[t];
    d_pos1[g*512 + id[t]] = t;
}

// ------------------- top-128-of-256 (bitonic, 256 threads x 1 elem) -------------------
__global__ void k_topk256(){
    __shared__ float v[256];
    __shared__ int   id[256];
    int g = blockIdx.x, t = threadIdx.x;
    v[t] = d_score[g*256 + t]; id[t] = t;
    __syncthreads();
    for (int k = 2; k <= 256; k <<= 1){
        for (int j = k >> 1; j > 0; j >>= 1){
            int ixj = t ^ j;
            if (ixj > t){
                float va = v[t], vb = v[ixj]; int ia = id[t], ib = id[ixj];
                bool aFirst = (va > vb) || (va == vb && ia < ib);
                bool want = ((t & k) == 0);
                if (aFirst != want){ v[t]=vb; v[ixj]=va; id[t]=ib; id[ixj]=ia; }
            }
            __syncthreads();
        }
    }
    if (t < 128) d_idx2[g*128 + t] = id[t];
}

// ------------------- gather kept rows + attention dot products -------------------
__global__ void k_gather(int oXin, int Nin, int K, int level,
                         const float* __restrict__ att, int oXout){
    const float* Xin = d_pool + oXin;
    float* Xout = d_pool + oXout;
    int gp = blockIdx.x;
    int g = gp / K;
    int node = g*Nin + (level == 1 ? d_idx1[gp] : d_idx2[gp]);
    int c = threadIdx.x; // 128
    float val = Xin[(size_t)node*128 + c];
    Xout[(size_t)gp*128 + c] = val;
    float qv = val*att[c], sv = val*att[128 + c];
    for (int o = 16; o > 0; o >>= 1){
        qv += __shfl_xor_sync(0xffffffffu, qv, o);
        sv += __shfl_xor_sync(0xffffffffu, sv, o);
    }
    __shared__ float smq[4], sms[4];
    int w = c >> 5, l = c & 31;
    if (l == 0){ smq[w] = qv; sms[w] = sv; }
    __syncthreads();
    if (c == 0){
        float q = smq[0]+smq[1]+smq[2]+smq[3];
        float s = sms[0]+sms[1]+sms[2]+sms[3];
        if (level == 1){ d_q1[gp] = q; d_s1v[gp] = s; }
        else           { d_q2[gp] = q; d_s2v[gp] = s; }
    }
}

// ------------------- build Ak from edge list via kept-position map -------------------
__global__ void k_buildAk(const int* __restrict__ src, const int* __restrict__ dst,
                          int oA1){
    float* A1 = d_pool + oA1;
    int e = blockIdx.x*blockDim.x + threadIdx.x;
    if (e >= Eg) return;
    int s = src[e], d = dst[e];
    int ps = d_pos1[s], pd = d_pos1[d];
    if (ps >= 0 && pd >= 0){
        int g = s >> 9;
        atomicAdd(&A1[((size_t)(g*Kp1) + ps)*Kp1 + pd], 1.0f);
    }
}

// ------------------- structure learning: A = softmax(leaky(q_i+s_j)) + lamb*A -------------------
__global__ void k_struct(int level, int oA, int K){
    const float* q = (level == 1) ? d_q1  : d_q2;
    const float* s = (level == 1) ? d_s1v : d_s2v;
    float* A = d_pool + oA;
    int row = blockIdx.x;
    int j = threadIdx.x;        // blockDim == K
    int g = row / K;
    float l = q[row] + s[g*K + j];
    l = l > 0.f ? l : NEG_SLOPE*l;
    __shared__ float redm[8], reds[8];
    __shared__ float fmx, fsum;
    float m = l;
    for (int o = 16; o > 0; o >>= 1) m = fmaxf(m, __shfl_xor_sync(0xffffffffu, m, o));
    int w = j >> 5, lane = j & 31;
    if (lane == 0) redm[w] = m;
    __syncthreads();
    if (j == 0){
        float mm = redm[0];
        for (int w2 = 1; w2 < (K >> 5); w2++) mm = fmaxf(mm, redm[w2]);
        fmx = mm;
    }
    __syncthreads();
    float e = __expf(l - fmx);
    float su = e;
    for (int o = 16; o > 0; o >>= 1) su += __shfl_xor_sync(0xffffffffu, su, o);
    if (lane == 0) reds[w] = su;
    __syncthreads();
    if (j == 0){
        float ss = reds[0];
        for (int w2 = 1; w2 < (K >> 5); w2++) ss += reds[w2];
        fsum = ss;
    }
    __syncthreads();
    float* Ar = &A[(size_t)row*K];
    Ar[j] = e / fsum + LAMBW * Ar[j];
}

// ------------------- readout (relu(max) || relu(mean)), optional accumulate -------------------
__global__ void k_readout(int oX, float* __restrict__ out, int K, int accumulate){
    const float* X = d_pool + oX;
    int g = blockIdx.x;
    int c = threadIdx.x;  // 128
    const float* Xg = X + (size_t)g*K*128;
    float mx = neg_inf(), sm = 0.f;
    #pragma unroll 4
    for (int p = 0; p < K; p++){
        float v = Xg[(size_t)p*128 + c];
        mx = fmaxf(mx, v); sm += v;
    }
    float o1 = fmaxf(mx, 0.f);
    float o2 = fmaxf(sm / (float)K, 0.f);
    if (accumulate){ out[g*256 + c] += o1; out[g*256 + 128 + c] += o2; }
    else           { out[g*256 + c]  = o1; out[g*256 + 128 + c]  = o2; }
}

// ------------------- rowsum -> dinv (whichOut: 0->d_dinvA, 1->d_dinvB) -------------------
__global__ void k_rowsum(int oA, int M, int addOne, int guardZero, int whichOut){
    const float* A = d_pool + oA;
    float* dinv = whichOut ? d_dinvB : d_dinvA;
    int row = (blockIdx.x*blockDim.x + threadIdx.x) >> 5;
    int lane = threadIdx.x & 31;
    if (row >= Bg*M) return;
    const float* Ar = A + (size_t)row*M;
    float s = 0.f;
    for (int j = lane; j < M; j += 32) s += Ar[j];
    for (int o = 16; o > 0; o >>= 1) s += __shfl_xor_sync(0xffffffffu, s, o);
    if (lane == 0){
        if (addOne) s += 1.f;
        float dv;
        if (guardZero && !(s > 0.f)) dv = 0.f;
        else dv = rsqrtf(fmaxf(s, 1e-12f));
        dinv[row] = dv;
    }
}

// ------------------- batched dense GCN aggregation (uvsel: 0->d_dinvA, 1->d_dinvB) -------------------
__global__ __launch_bounds__(256) void k_dense_gcn(int oA, int oX, int uvsel,
        const float* __restrict__ bias, int oO, int M, int addSelf, int doRelu){
    const float* A = d_pool + oA;
    const float* X = d_pool + oX;
    float* O = d_pool + oO;
    const float* uv = uvsel ? d_dinvB : d_dinvA;
    int tilesPer = M / 32;
    int g = blockIdx.x / tilesPer;
    int row0 = (blockIdx.x % tilesPer) * 32;
    __shared__ float As[32][32];
    __shared__ float Xs[32][128];
    int ty = threadIdx.x >> 5, tx = threadIdx.x & 31;
    float acc[4][4];
    #pragma unroll
    for (int r = 0; r < 4; r++){ acc[r][0]=acc[r][1]=acc[r][2]=acc[r][3]=0.f; }
    const float* Ag = A + (size_t)g*M*M;
    const float* Xg = X + (size_t)g*M*128;
    const float* vg = uv + g*M;
    for (int jb = 0; jb < M; jb += 32){
        #pragma unroll
        for (int t = 0; t < 4; t++){
            int e = threadIdx.x + 256*t; int r = e >> 5, j = e & 31;
            As[r][j] = Ag[(size_t)(row0+r)*M + jb + j];
        }
        #pragma unroll
        for (int t = 0; t < 16; t++){
            int e = threadIdx.x + 256*t; int jj = e >> 7, c = e & 127;
            Xs[jj][c] = Xg[(size_t)(jb+jj)*128 + c] * vg[jb+jj];
        }
        __syncthreads();
        #pragma unroll
        for (int jj = 0; jj < 32; jj++){
            float4 xv = *reinterpret_cast<const float4*>(&Xs[jj][tx*4]);
            #pragma unroll
            for (int r = 0; r < 4; r++){
                float a = As[ty*4 + r][jj];
                acc[r][0] += a*xv.x; acc[r][1] += a*xv.y;
                acc[r][2] += a*xv.z; acc[r][3] += a*xv.w;
            }
        }
        __syncthreads();
    }
    #pragma unroll
    for (int r = 0; r < 4; r++){
        int i = row0 + ty*4 + r;
        int gi = g*M + i;
        float uu = vg[i];
        float vi = vg[i];
        #pragma unroll
        for (int c4 = 0; c4 < 4; c4++){
            int c = tx*4 + c4;
            float val = acc[r][c4];
            if (addSelf) val += vi * Xg[(size_t)i*128 + c];
            val *= uu;
            if (bias) val += bias[c];
            if (doRelu) val = fmaxf(val, 0.f);
            O[(size_t)gi*128 + c] = val;
        }
    }
}

// ------------------- |Xa - Xb| row sums -> d_score -------------------
__global__ void k_absdiff(int oXa, int oXb, int rows){
    const float* Xa = d_pool + oXa;
    const float* Xb = d_pool + oXb;
    int row = (blockIdx.x*blockDim.x + threadIdx.x) >> 5;
    int lane = threadIdx.x & 31;
    if (row >= rows) return;
    const float* a = Xa + (size_t)row*128;
    const float* b = Xb + (size_t)row*128;
    float s = fabsf(a[lane]-b[lane]) + fabsf(a[lane+32]-b[lane+32])
            + fabsf(a[lane+64]-b[lane+64]) + fabsf(a[lane+96]-b[lane+96]);
    for (int o = 16; o > 0; o >>= 1) s += __shfl_xor_sync(0xffffffffu, s, o);
    if (lane == 0) d_score[row] = s;
}

// ------------------- A1k gather -------------------
__global__ void k_gatherA2(int oA1, int oA2){
    const float* A1 = d_pool + oA1;
    float* A2 = d_pool + oA2;
    int gp = blockIdx.x;        // B*K2
    int g = gp >> 7, t = threadIdx.x; // 128
    int ip = d_idx2[gp];
    int iq = d_idx2[g*Kp2 + t];
    A2[(size_t)gp*Kp2 + t] = A1[((size_t)(g*Kp1) + ip)*Kp1 + iq];
}

// ------------------- launch: ONLY plain default-stream kernel launches -------------------
extern "C" void kernel_launch(void* const* d_in, const int* in_sizes, int n_in,
                              void* d_out, int out_size){
    const float* x    = (const float*)d_in[0];
    const float* W1   = (const float*)d_in[1];
    const float* b1   = (const float*)d_in[2];
    const float* W2   = (const float*)d_in[3];
    const float* b2   = (const float*)d_in[4];
    const float* W3   = (const float*)d_in[5];
    const float* b3   = (const float*)d_in[6];
    const float* att1 = (const float*)d_in[7];
    const float* att2 = (const float*)d_in[8];
    const int* esrc   = (const int*)d_in[9];
    const int* edst   = (const int*)d_in[10];
    float* out = (float*)d_out;

    // ---- CSR build ----
    k_zero_deg<<<(BN + 255) / 256, 256>>>();
    k_degree<<<(Eg + 255) / 256, 256>>>(edst);
    k_dinv<<<(BN + 255) / 256, 256>>>();
    k_scan1<<<BN / 256, 256>>>();
    k_scan2<<<1, 32>>>();
    k_scan3<<<BN / 256, 256>>>();
    k_fill<<<(Eg + 255) / 256, 256>>>(esrc, edst);

    // ---- conv1: xagg = norm-agg(x); h = relu(xagg@W1 + b1) IN-PLACE; info1 ----
    k_aggx<<<(BN * 32) / 256, 256>>>(x, OFF_XAGG);
    k_gemm<<<BN / 64, 256>>>(OFF_XAGG, W1, OFF_H, BN, b1, 1);
    k_info1<<<(BN * 32) / 256, 256>>>(OFF_H);

    // ---- pool1 ----
    k_topk512<<<Bg, 256>>>();
    k_gather<<<Bg * Kp1, 128>>>(OFF_H, Nn, Kp1, 1, att1, OFF_HK);
    k_zero_pool<<<4096, 256>>>(OFF_A1, Bg * Kp1 * Kp1);   // h dead -> A1
    k_buildAk<<<(Eg + 255) / 256, 256>>>(esrc, edst, OFF_A1);
    k_struct<<<Bg * Kp1, Kp1>>>(1, OFF_A1, Kp1);
    k_readout<<<Bg, 128>>>(OFF_HK, out, Kp1, 0);

    // ---- conv2: hw = hk@W2 IN-PLACE; h2 = gcn(A1, hw) ----
    k_gemm<<<(Bg * Kp1) / 64, 256>>>(OFF_HK, W2, OFF_HW, Bg * Kp1, (const float*)0, 0);
    k_rowsum<<<(Bg * Kp1 * 32) / 256, 256>>>(OFF_A1, Kp1, 1, 0, 0);
    k_dense_gcn<<<Bg * (Kp1 / 32), 256>>>(OFF_A1, OFF_HW, 0, b2, OFF_H2, Kp1, 1, 1);

    // ---- info2: smooth -> hw region (dead); score = |h2 - smooth| ----
    k_rowsum<<<(Bg * Kp1 * 32) / 256, 256>>>(OFF_A1, Kp1, 0, 1, 1);
    k_dense_gcn<<<Bg * (Kp1 / 32), 256>>>(OFF_A1, OFF_H2, 1, (const float*)0, OFF_HW, Kp1, 0, 0);
    k_absdiff<<<(Bg * Kp1 * 32) / 256, 256>>>(OFF_H2, OFF_HW, Bg * Kp1);

    // ---- pool2: h2k + A2 into hw region (smooth dead) ----
    k_topk256<<<Bg, 256>>>();
    k_gather<<<Bg * Kp2, 128>>>(OFF_H2, Kp1, Kp2, 2, att2, OFF_H2K);
    k_gatherA2<<<Bg * Kp2, 128>>>(OFF_A1, OFF_A2);
    k_struct<<<Bg * Kp2, Kp2>>>(2, OFF_A2, Kp2);
    k_readout<<<Bg, 128>>>(OFF_H2K, out, Kp2, 1);

    // ---- conv3: hw3 = h2k@W3 IN-PLACE; h3 = gcn(A2, hw3) -> h2 region (dead) ----
    k_gemm<<<(Bg * Kp2) / 64, 256>>>(OFF_H2K, W3, OFF_H2K, Bg * Kp2, (const float*)0, 0);
    k_rowsum<<<(Bg * Kp2 * 32) / 256, 256>>>(OFF_A2, Kp2, 1, 0, 0);
    k_dense_gcn<<<Bg * (Kp2 / 32), 256>>>(OFF_A2, OFF_H2K, 0, b3, OFF_H3, Kp2, 1, 1);
    k_readout<<<Bg, 128>>>(OFF_H3, out, Kp2, 1);
}

// round 15
// speedup vs baseline: 1.0243x; 1.0243x over previous
#include <cuda_runtime.h>
#include <stdlib.h>

#define Bg 256
#define Nn 512
#define Fd 128
#define Eg 2097152
#define Kp1 256
#define Kp2 128
#define BN (Bg*Nn)
#define NEG_SLOPE 0.2f
#define LAMBW 1.0f

// Only ctor: set EAGER module loading. NO CUDA calls pre-main (R12-verified).
__attribute__((constructor))
static void hx_env(){ setenv("CUDA_MODULE_LOADING", "EAGER", 1); }

// ------------------- scratch pool (R12-verified liveness) -------------------
//  P1 [0,16777216):          xagg -> h (in-place x@W1) -> A1
//  P2 [16777216,25165824):   hk -> hw (in-place hk@W2) -> h2k|A2
//  P3 [25165824,33554432):   h2 -> h3
#define OFF_XAGG 0
#define OFF_H    0
#define OFF_A1   0
#define OFF_HK   16777216
#define OFF_HW   16777216
#define OFF_H2   25165824
#define OFF_H2K  16777216
#define OFF_A2   20971520
#define OFF_H3   25165824
#define POOL_FLOATS 33554432
__device__ __align__(16) float d_pool[POOL_FLOATS];

__device__ int   d_deg[BN];
__device__ float d_dinv1[BN];
__device__ float d_dinv0[BN];
__device__ int   d_rowptr[BN+1];
__device__ int   d_cursor[BN];
__device__ int   d_csrsrc[Eg];
__device__ int   d_blocksum[BN/256];
__device__ float d_score[BN];
__device__ int   d_idx1[Bg*Kp1];
__device__ int   d_pos1[BN];
__device__ float d_q1[Bg*Kp1];
__device__ float d_s1v[Bg*Kp1];
__device__ float d_dinvA[Bg*Kp1];
__device__ float d_dinvB[Bg*Kp1];
__device__ int   d_idx2[Bg*Kp2];
__device__ float d_q2[Bg*Kp2];
__device__ float d_s2v[Bg*Kp2];

__device__ __forceinline__ float neg_inf(){ return __int_as_float(0xff800000); }

// ------------------- small utility kernels -------------------
__global__ void k_zero_deg(){
    int i = blockIdx.x*blockDim.x + threadIdx.x;
    if (i < BN) d_deg[i] = 0;
}
__global__ void k_zero_pool4(int off, int n4){
    float4* p = reinterpret_cast<float4*>(d_pool + off);
    float4 z = make_float4(0.f,0.f,0.f,0.f);
    for (int i = blockIdx.x*blockDim.x + threadIdx.x; i < n4; i += gridDim.x*blockDim.x)
        p[i] = z;
}
__global__ void k_degree(const int* __restrict__ dst){
    int e = blockIdx.x*blockDim.x + threadIdx.x;
    if (e < Eg) atomicAdd(&d_deg[dst[e]], 1);
}
__global__ void k_dinv(){
    int i = blockIdx.x*blockDim.x + threadIdx.x;
    if (i >= BN) return;
    int dg = d_deg[i];
    d_dinv1[i] = rsqrtf((float)dg + 1.0f);
    d_dinv0[i] = dg > 0 ? rsqrtf((float)dg) : 0.f;
}
__global__ void k_scan1(){
    __shared__ int s[256];
    int i = blockIdx.x*256 + threadIdx.x;
    int v = d_deg[i];
    s[threadIdx.x] = v;
    __syncthreads();
    for (int off = 1; off < 256; off <<= 1){
        int t = (threadIdx.x >= off) ? s[threadIdx.x - off] : 0;
        __syncthreads();
        s[threadIdx.x] += t;
        __syncthreads();
    }
    d_rowptr[i] = s[threadIdx.x] - v;
    if (threadIdx.x == 255) d_blocksum[blockIdx.x] = s[255];
}
__global__ void k_scan2(){
    if (threadIdx.x == 0){
        int acc = 0;
        for (int i = 0; i < BN/256; i++){
            int v = d_blocksum[i];
            d_blocksum[i] = acc;
            acc += v;
        }
    }
}
__global__ void k_scan3(){
    int i = blockIdx.x*256 + threadIdx.x;
    int rp = d_rowptr[i] + d_blocksum[blockIdx.x];
    d_rowptr[i] = rp;
    d_cursor[i] = rp;
    if (i == 0) d_rowptr[BN] = Eg;
}
__global__ void k_fill(const int* __restrict__ src, const int* __restrict__ dst){
    int e = blockIdx.x*blockDim.x + threadIdx.x;
    if (e >= Eg) return;
    int p = atomicAdd(&d_cursor[dst[e]], 1);
    d_csrsrc[p] = src[e];
}

// ------------------- normalized aggregation of raw x (warp/node, float4) -------------------
__global__ void k_aggx(const float* __restrict__ x, int oXagg){
    float* xagg = d_pool + oXagg;
    int node = (blockIdx.x*blockDim.x + threadIdx.x) >> 5;
    int lane = threadIdx.x & 31;
    if (node >= BN) return;
    float di = d_dinv1[node];
    int beg = d_rowptr[node], end = d_rowptr[node+1];
    float4 acc = make_float4(0.f,0.f,0.f,0.f);
    for (int e = beg; e < end; e++){
        int s = d_csrsrc[e];
        float c = d_dinv1[s] * di;
        float4 xv = *reinterpret_cast<const float4*>(&x[(size_t)s*128 + lane*4]);
        acc.x += xv.x*c; acc.y += xv.y*c; acc.z += xv.z*c; acc.w += xv.w*c;
    }
    float4 xs = *reinterpret_cast<const float4*>(&x[(size_t)node*128 + lane*4]);
    float sc = di*di;
    acc.x += xs.x*sc; acc.y += xs.y*sc; acc.z += xs.z*sc; acc.w += xs.w*sc;
    *reinterpret_cast<float4*>(&xagg[(size_t)node*128 + lane*4]) = acc;
}

// ------------------- GEMM 128x128 tile, 8x8/thread: O = act(X@W + bias); in-place OK -------------------
__global__ __launch_bounds__(256) void k_gemm(int oX, const float* __restrict__ W,
                                              int oO, int M,
                                              const float* __restrict__ bias,
                                              int doRelu){
    const float* X = d_pool + oX;
    float* O = d_pool + oO;
    __shared__ float Xs[128][17];
    __shared__ float Ws[16][128];
    int tx = threadIdx.x & 15, ty = threadIdx.x >> 4;
    int row0 = blockIdx.x * 128;
    float acc[8][8];
    #pragma unroll
    for (int r = 0; r < 8; r++)
        #pragma unroll
        for (int c = 0; c < 8; c++) acc[r][c] = 0.f;
    for (int kb = 0; kb < 128; kb += 16){
        #pragma unroll
        for (int t = 0; t < 8; t++){
            int e = threadIdx.x + 256*t;       // 0..2047
            int i = e >> 4, k = e & 15;
            Xs[i][k] = X[(size_t)(row0+i)*128 + kb + k];
        }
        #pragma unroll
        for (int t = 0; t < 8; t++){
            int e = threadIdx.x + 256*t;
            int kk = e >> 7, c = e & 127;
            Ws[kk][c] = W[(size_t)(kb+kk)*128 + c];
        }
        __syncthreads();
        #pragma unroll
        for (int kk = 0; kk < 16; kk++){
            float xr[8], wr[8];
            #pragma unroll
            for (int r = 0; r < 8; r++) xr[r] = Xs[ty*8+r][kk];
            float4 w0 = *reinterpret_cast<const float4*>(&Ws[kk][tx*8]);
            float4 w1 = *reinterpret_cast<const float4*>(&Ws[kk][tx*8+4]);
            wr[0]=w0.x; wr[1]=w0.y; wr[2]=w0.z; wr[3]=w0.w;
            wr[4]=w1.x; wr[5]=w1.y; wr[6]=w1.z; wr[7]=w1.w;
            #pragma unroll
            for (int r = 0; r < 8; r++)
                #pragma unroll
                for (int c = 0; c < 8; c++)
                    acc[r][c] += xr[r]*wr[c];
        }
        __syncthreads();
    }
    float bv[8];
    #pragma unroll
    for (int c = 0; c < 8; c++) bv[c] = bias ? bias[tx*8+c] : 0.f;
    #pragma unroll
    for (int r = 0; r < 8; r++){
        float v[8];
        #pragma unroll
        for (int c = 0; c < 8; c++){
            float t = acc[r][c] + bv[c];
            v[c] = doRelu ? fmaxf(t, 0.f) : t;
        }
        float* orow = &O[(size_t)(row0+ty*8+r)*128 + tx*8];
        *reinterpret_cast<float4*>(orow)     = make_float4(v[0],v[1],v[2],v[3]);
        *reinterpret_cast<float4*>(orow + 4) = make_float4(v[4],v[5],v[6],v[7]);
    }
}

// ------------------- info-score (edge, float4 gathers) -------------------
__global__ void k_info1(int oH){
    const float* h = d_pool + oH;
    int node = (blockIdx.x*blockDim.x + threadIdx.x) >> 5;
    int lane = threadIdx.x & 31;
    if (node >= BN) return;
    float di = d_dinv0[node];
    int beg = d_rowptr[node], end = d_rowptr[node+1];
    float4 acc = make_float4(0.f,0.f,0.f,0.f);
    for (int e = beg; e < end; e++){
        int s = d_csrsrc[e];
        float c = d_dinv0[s] * di;
        float4 hv = *reinterpret_cast<const float4*>(&h[(size_t)s*128 + lane*4]);
        acc.x += hv.x*c; acc.y += hv.y*c; acc.z += hv.z*c; acc.w += hv.w*c;
    }
    float4 hs = *reinterpret_cast<const float4*>(&h[(size_t)node*128 + lane*4]);
    float sum = fabsf(hs.x-acc.x) + fabsf(hs.y-acc.y) + fabsf(hs.z-acc.z) + fabsf(hs.w-acc.w);
    for (int o = 16; o > 0; o >>= 1) sum += __shfl_xor_sync(0xffffffffu, sum, o);
    if (lane == 0) d_score[node] = sum;
}

// ------------------- top-256-of-512 (bitonic, 256 threads x 2 elems) -------------------
__global__ void k_topk512(){
    __shared__ float v[512];
    __shared__ int   id[512];
    int g = blockIdx.x, t = threadIdx.x;
    v[t]       = d_score[g*512 + t];       id[t]       = t;
    v[t + 256] = d_score[g*512 + t + 256]; id[t + 256] = t + 256;
    __syncthreads();
    for (int k = 2; k <= 512; k <<= 1){
        for (int j = k >> 1; j > 0; j >>= 1){
            #pragma unroll
            for (int half = 0; half < 2; half++){
                int i = t + half*256;
                int ixj = i ^ j;
                if (ixj > i){
                    float va = v[i], vb = v[ixj]; int ia = id[i], ib = id[ixj];
                    bool aFirst = (va > vb) || (va == vb && ia < ib);
                    bool want = ((i & k) == 0);
                    if (aFirst != want){ v[i]=vb; v[ixj]=va; id[i]=ib; id[ixj]=ia; }
                }
            }
            __syncthreads();
        }
    }
    d_pos1[g*512 + t] = -1;
    d_pos1[g*512 + t + 256] = -1;
    __syncthreads();
    d_idx1[g*256 + t] = id[t];
    d_pos1[g*512 + id[t]] = t;
}

// ------------------- top-128-of-256 -------------------
__global__ void k_topk256(){
    __shared__ float v[256];
    __shared__ int   id[256];
    int g = blockIdx.x, t = threadIdx.x;
    v[t] = d_score[g*256 + t]; id[t] = t;
    __syncthreads();
    for (int k = 2; k <= 256; k <<= 1){
        for (int j = k >> 1; j > 0; j >>= 1){
            int ixj = t ^ j;
            if (ixj > t){
                float va = v[t], vb = v[ixj]; int ia = id[t], ib = id[ixj];
                bool aFirst = (va > vb) || (va == vb && ia < ib);
                bool want = ((t & k) == 0);
                if (aFirst != want){ v[t]=vb; v[ixj]=va; id[t]=ib; id[ixj]=ia; }
            }
            __syncthreads();
        }
    }
    if (t < 128) d_idx2[g*128 + t] = id[t];
}

// ------------------- gather kept rows + attention dot products -------------------
__global__ void k_gather(int oXin, int Nin, int K, int level,
                         const float* __restrict__ att, int oXout){
    const float* Xin = d_pool + oXin;
    float* Xout = d_pool + oXout;
    int gp = blockIdx.x;
    int g = gp / K;
    int node = g*Nin + (level == 1 ? d_idx1[gp] : d_idx2[gp]);
    int c = threadIdx.x; // 128
    float val = Xin[(size_t)node*128 + c];
    Xout[(size_t)gp*128 + c] = val;
    float qv = val*att[c], sv = val*att[128 + c];
    for (int o = 16; o > 0; o >>= 1){
        qv += __shfl_xor_sync(0xffffffffu, qv, o);
        sv += __shfl_xor_sync(0xffffffffu, sv, o);
    }
    __shared__ float smq[4], sms[4];
    int w = c >> 5, l = c & 31;
    if (l == 0){ smq[w] = qv; sms[w] = sv; }
    __syncthreads();
    if (c == 0){
        float q = smq[0]+smq[1]+smq[2]+smq[3];
        float s = sms[0]+sms[1]+sms[2]+sms[3];
        if (level == 1){ d_q1[gp] = q; d_s1v[gp] = s; }
        else           { d_q2[gp] = q; d_s2v[gp] = s; }
    }
}

// ------------------- build Ak from edge list via kept-position map -------------------
__global__ void k_buildAk(const int* __restrict__ src, const int* __restrict__ dst,
                          int oA1){
    float* A1 = d_pool + oA1;
    int e = blockIdx.x*blockDim.x + threadIdx.x;
    if (e >= Eg) return;
    int s = src[e], d = dst[e];
    int ps = d_pos1[s], pd = d_pos1[d];
    if (ps >= 0 && pd >= 0){
        int g = s >> 9;
        atomicAdd(&A1[((size_t)(g*Kp1) + ps)*Kp1 + pd], 1.0f);
    }
}

// ------------------- structure learning + FUSED rowsum->dinv -------------------
// A_new = softmax(leaky(q_i+s_j)) + lamb*A_old.
// rowsum(A_new) = 1 + lamb*rowsum(A_old)  ->
//   dinvA = rsqrt(2 + rs_old)   (conv GCN: +1 self loop)
//   dinvB = rsqrt(1 + rs_old)   (info score; rowsum >= 1 > 0, guard moot)
__global__ void k_struct(int level, int oA, int K){
    const float* q = (level == 1) ? d_q1  : d_q2;
    const float* s = (level == 1) ? d_s1v : d_s2v;
    float* A = d_pool + oA;
    int row = blockIdx.x;
    int j = threadIdx.x;        // blockDim == K
    int g = row / K;
    float* Ar = &A[(size_t)row*K];
    float aold = Ar[j];
    float l = q[row] + s[g*K + j];
    l = l > 0.f ? l : NEG_SLOPE*l;
    __shared__ float redm[8], reds[8], redo[8];
    __shared__ float fmx, fsum;
    float m = l;
    for (int o = 16; o > 0; o >>= 1) m = fmaxf(m, __shfl_xor_sync(0xffffffffu, m, o));
    int w = j >> 5, lane = j & 31;
    if (lane == 0) redm[w] = m;
    __syncthreads();
    if (j == 0){
        float mm = redm[0];
        for (int w2 = 1; w2 < (K >> 5); w2++) mm = fmaxf(mm, redm[w2]);
        fmx = mm;
    }
    __syncthreads();
    float e = __expf(l - fmx);
    float su = e, so = aold;
    for (int o = 16; o > 0; o >>= 1){
        su += __shfl_xor_sync(0xffffffffu, su, o);
        so += __shfl_xor_sync(0xffffffffu, so, o);
    }
    if (lane == 0){ reds[w] = su; redo[w] = so; }
    __syncthreads();
    if (j == 0){
        float ss = reds[0], rs = redo[0];
        for (int w2 = 1; w2 < (K >> 5); w2++){ ss += reds[w2]; rs += redo[w2]; }
        fsum = ss;
        d_dinvA[row] = rsqrtf(2.0f + LAMBW*rs);
        d_dinvB[row] = rsqrtf(1.0f + LAMBW*rs);
    }
    __syncthreads();
    Ar[j] = e / fsum + LAMBW * aold;
}

// ------------------- readout (relu(max) || relu(mean)), optional accumulate -------------------
__global__ void k_readout(int oX, float* __restrict__ out, int K, int accumulate){
    const float* X = d_pool + oX;
    int g = blockIdx.x;
    int c = threadIdx.x;  // 128
    const float* Xg = X + (size_t)g*K*128;
    float mx = neg_inf(), sm = 0.f;
    #pragma unroll 4
    for (int p = 0; p < K; p++){
        float v = Xg[(size_t)p*128 + c];
        mx = fmaxf(mx, v); sm += v;
    }
    float o1 = fmaxf(mx, 0.f);
    float o2 = fmaxf(sm / (float)K, 0.f);
    if (accumulate){ out[g*256 + c] += o1; out[g*256 + 128 + c] += o2; }
    else           { out[g*256 + c]  = o1; out[g*256 + 128 + c]  = o2; }
}

// ------------------- batched dense GCN aggregation -------------------
// normal:    O[i][c] = act( uv[i]*( sum_j A[i][j]*uv[j]*X[j][c] + addSelf*uv[i]*X[i][c] ) + bias[c] )
// scoreMode: d_score[gi] = sum_c | X[i][c] - uv[i]*sum_j A[i][j]*uv[j]*X[j][c] |   (no O store)
__global__ __launch_bounds__(256) void k_dense_gcn(int oA, int oX, int uvsel,
        const float* __restrict__ bias, int oO, int M, int addSelf, int doRelu,
        int scoreMode){
    const float* A = d_pool + oA;
    const float* X = d_pool + oX;
    float* O = d_pool + oO;
    const float* uv = uvsel ? d_dinvB : d_dinvA;
    int tilesPer = M / 32;
    int g = blockIdx.x / tilesPer;
    int row0 = (blockIdx.x % tilesPer) * 32;
    __shared__ float As[32][32];
    __shared__ float Xs[32][128];
    int ty = threadIdx.x >> 5, tx = threadIdx.x & 31;
    float acc[4][4];
    #pragma unroll
    for (int r = 0; r < 4; r++){ acc[r][0]=acc[r][1]=acc[r][2]=acc[r][3]=0.f; }
    const float* Ag = A + (size_t)g*M*M;
    const float* Xg = X + (size_t)g*M*128;
    const float* vg = uv + g*M;
    for (int jb = 0; jb < M; jb += 32){
        {   // As: 32x32 floats = 256 float4, one per thread
            int e = threadIdx.x; int r = e >> 3, j4 = e & 7;
            *reinterpret_cast<float4*>(&As[r][j4*4]) =
                *reinterpret_cast<const float4*>(&Ag[(size_t)(row0+r)*M + jb + j4*4]);
        }
        #pragma unroll
        for (int t = 0; t < 4; t++){ // Xs: 32x128 floats = 1024 float4
            int e = threadIdx.x + 256*t; int jj = e >> 5, c4 = e & 31;
            float vj = vg[jb+jj];
            float4 xv = *reinterpret_cast<const float4*>(&Xg[(size_t)(jb+jj)*128 + c4*4]);
            xv.x *= vj; xv.y *= vj; xv.z *= vj; xv.w *= vj;
            *reinterpret_cast<float4*>(&Xs[jj][c4*4]) = xv;
        }
        __syncthreads();
        #pragma unroll
        for (int jj = 0; jj < 32; jj++){
            float4 xv = *reinterpret_cast<const float4*>(&Xs[jj][tx*4]);
            #pragma unroll
            for (int r = 0; r < 4; r++){
                float a = As[ty*4 + r][jj];
                acc[r][0] += a*xv.x; acc[r][1] += a*xv.y;
                acc[r][2] += a*xv.z; acc[r][3] += a*xv.w;
            }
        }
        __syncthreads();
    }
    if (scoreMode){
        #pragma unroll
        for (int r = 0; r < 4; r++){
            int i = row0 + ty*4 + r;
            int gi = g*M + i;
            float uu = vg[i];
            float p = 0.f;
            #pragma unroll
            for (int c4 = 0; c4 < 4; c4++){
                int c = tx*4 + c4;
                p += fabsf(Xg[(size_t)i*128 + c] - uu*acc[r][c4]);
            }
            for (int o = 16; o > 0; o >>= 1) p += __shfl_xor_sync(0xffffffffu, p, o);
            if (tx == 0) d_score[gi] = p;
        }
    } else {
        #pragma unroll
        for (int r = 0; r < 4; r++){
            int i = row0 + ty*4 + r;
            int gi = g*M + i;
            float uu = vg[i];
            #pragma unroll
            for (int c4 = 0; c4 < 4; c4++){
                int c = tx*4 + c4;
                float val = acc[r][c4];
                if (addSelf) val += vg[i] * Xg[(size_t)i*128 + c];
                val *= uu;
                if (bias) val += bias[c];
                if (doRelu) val = fmaxf(val, 0.f);
                O[(size_t)gi*128 + c] = val;
            }
        }
    }
}

// ------------------- A1k gather -------------------
__global__ void k_gatherA2(int oA1, int oA2){
    const float* A1 = d_pool + oA1;
    float* A2 = d_pool + oA2;
    int gp = blockIdx.x;
    int g = gp >> 7, t = threadIdx.x;
    int ip = d_idx2[gp];
    int iq = d_idx2[g*Kp2 + t];
    A2[(size_t)gp*Kp2 + t] = A1[((size_t)(g*Kp1) + ip)*Kp1 + iq];
}

// ------------------- launch -------------------
extern "C" void kernel_launch(void* const* d_in, const int* in_sizes, int n_in,
                              void* d_out, int out_size){
    const float* x    = (const float*)d_in[0];
    const float* W1   = (const float*)d_in[1];
    const float* b1   = (const float*)d_in[2];
    const float* W2   = (const float*)d_in[3];
    const float* b2   = (const float*)d_in[4];
    const float* W3   = (const float*)d_in[5];
    const float* b3   = (const float*)d_in[6];
    const float* att1 = (const float*)d_in[7];
    const float* att2 = (const float*)d_in[8];
    const int* esrc   = (const int*)d_in[9];
    const int* edst   = (const int*)d_in[10];
    float* out = (float*)d_out;

    // ---- CSR build ----
    k_zero_deg<<<(BN + 255) / 256, 256>>>();
    k_degree<<<(Eg + 255) / 256, 256>>>(edst);
    k_dinv<<<(BN + 255) / 256, 256>>>();
    k_scan1<<<BN / 256, 256>>>();
    k_scan2<<<1, 32>>>();
    k_scan3<<<BN / 256, 256>>>();
    k_fill<<<(Eg + 255) / 256, 256>>>(esrc, edst);

    // ---- conv1: xagg = norm-agg(x); h = relu(xagg@W1 + b1) IN-PLACE; info1 ----
    k_aggx<<<(BN * 32) / 256, 256>>>(x, OFF_XAGG);
    k_gemm<<<BN / 128, 256>>>(OFF_XAGG, W1, OFF_H, BN, b1, 1);
    k_info1<<<(BN * 32) / 256, 256>>>(OFF_H);

    // ---- pool1 ----
    k_topk512<<<Bg, 256>>>();
    k_gather<<<Bg * Kp1, 128>>>(OFF_H, Nn, Kp1, 1, att1, OFF_HK);
    k_zero_pool4<<<2048, 256>>>(OFF_A1, (Bg * Kp1 * Kp1) / 4);   // h dead -> A1
    k_buildAk<<<(Eg + 255) / 256, 256>>>(esrc, edst, OFF_A1);
    k_struct<<<Bg * Kp1, Kp1>>>(1, OFF_A1, Kp1);                  // also writes dinvA/dinvB
    k_readout<<<Bg, 128>>>(OFF_HK, out, Kp1, 0);

    // ---- conv2: hw = hk@W2 IN-PLACE; h2 = gcn(A1, hw) ----
    k_gemm<<<(Bg * Kp1) / 128, 256>>>(OFF_HK, W2, OFF_HW, Bg * Kp1, (const float*)0, 0);
    k_dense_gcn<<<Bg * (Kp1 / 32), 256>>>(OFF_A1, OFF_HW, 0, b2, OFF_H2, Kp1, 1, 1, 0);

    // ---- info2 (fused smooth+absdiff -> d_score) ----
    k_dense_gcn<<<Bg * (Kp1 / 32), 256>>>(OFF_A1, OFF_H2, 1, (const float*)0, OFF_HW, Kp1, 0, 0, 1);

    // ---- pool2 ----
    k_topk256<<<Bg, 256>>>();
    k_gather<<<Bg * Kp2, 128>>>(OFF_H2, Kp1, Kp2, 2, att2, OFF_H2K);
    k_gatherA2<<<Bg * Kp2, 128>>>(OFF_A1, OFF_A2);
    k_struct<<<Bg * Kp2, Kp2>>>(2, OFF_A2, Kp2);                  // writes dinvA for conv3
    k_readout<<<Bg, 128>>>(OFF_H2K, out, Kp2, 1);

    // ---- conv3: hw3 = h2k@W3 IN-PLACE; h3 = gcn(A2, hw3) ----
    k_gemm<<<(Bg * Kp2) / 128, 256>>>(OFF_H2K, W3, OFF_H2K, Bg * Kp2, (const float*)0, 0);
    k_dense_gcn<<<Bg * (Kp2 / 32), 256>>>(OFF_A2, OFF_H2K, 0, b3, OFF_H3, Kp2, 1, 1, 0);
    k_readout<<<Bg, 128>>>(OFF_H3, out, Kp2, 1);
}

// round 17
// speedup vs baseline: 1.1179x; 1.0914x over previous
#include <cuda_runtime.h>
#include <stdlib.h>

#define Bg 256
#define Nn 512
#define Fd 128
#define Eg 2097152
#define Kp1 256
#define Kp2 128
#define BN (Bg*Nn)
#define NEG_SLOPE 0.2f
#define LAMBW 1.0f

// Only ctor: set EAGER module loading. NO CUDA calls pre-main (R12-verified).
__attribute__((constructor))
static void hx_env(){ setenv("CUDA_MODULE_LOADING", "EAGER", 1); }

// ------------------- scratch pool (R12-verified liveness) -------------------
#define OFF_XAGG 0
#define OFF_H    0
#define OFF_A1   0
#define OFF_HK   16777216
#define OFF_HW   16777216
#define OFF_H2   25165824
#define OFF_H2K  16777216
#define OFF_A2   20971520
#define OFF_H3   25165824
#define POOL_FLOATS 33554432
__device__ __align__(16) float d_pool[POOL_FLOATS];

__device__ int   d_deg[BN];
__device__ float d_dinv1[BN];
__device__ float d_dinv0[BN];
__device__ int   d_rowptr[BN+1];
__device__ int   d_cursor[BN];
__device__ int   d_csrsrc[Eg];
__device__ int   d_blocksum[BN/256];
__device__ float d_score[BN];
__device__ int   d_idx1[Bg*Kp1];
__device__ int   d_pos1[BN];
__device__ float d_q1[Bg*Kp1];
__device__ float d_s1v[Bg*Kp1];
__device__ float d_dinvA[Bg*Kp1];
__device__ float d_dinvB[Bg*Kp1];
__device__ int   d_idx2[Bg*Kp2];
__device__ float d_q2[Bg*Kp2];
__device__ float d_s2v[Bg*Kp2];

__device__ __forceinline__ float neg_inf(){ return __int_as_float(0xff800000); }

// ------------------- small utility kernels -------------------
__global__ void k_zero_deg(){
    int i = blockIdx.x*blockDim.x + threadIdx.x;
    if (i < BN) d_deg[i] = 0;
}
__global__ void k_zero_pool4(int off, int n4){
    float4* p = reinterpret_cast<float4*>(d_pool + off);
    float4 z = make_float4(0.f,0.f,0.f,0.f);
    for (int i = blockIdx.x*blockDim.x + threadIdx.x; i < n4; i += gridDim.x*blockDim.x)
        p[i] = z;
}
__global__ void k_degree(const int* __restrict__ dst){
    int e = blockIdx.x*blockDim.x + threadIdx.x;
    if (e < Eg) atomicAdd(&d_deg[dst[e]], 1);
}
// scan1 also produces dinv1/dinv0 (fused former k_dinv)
__global__ void k_scan1(){
    __shared__ int s[256];
    int i = blockIdx.x*256 + threadIdx.x;
    int v = d_deg[i];
    d_dinv1[i] = rsqrtf((float)v + 1.0f);
    d_dinv0[i] = v > 0 ? rsqrtf((float)v) : 0.f;
    s[threadIdx.x] = v;
    __syncthreads();
    for (int off = 1; off < 256; off <<= 1){
        int t = (threadIdx.x >= off) ? s[threadIdx.x - off] : 0;
        __syncthreads();
        s[threadIdx.x] += t;
        __syncthreads();
    }
    d_rowptr[i] = s[threadIdx.x] - v;
    if (threadIdx.x == 255) d_blocksum[blockIdx.x] = s[255];
}
__global__ void k_scan2(){
    if (threadIdx.x == 0){
        int acc = 0;
        for (int i = 0; i < BN/256; i++){
            int v = d_blocksum[i];
            d_blocksum[i] = acc;
            acc += v;
        }
    }
}
__global__ void k_scan3(){
    int i = blockIdx.x*256 + threadIdx.x;
    int rp = d_rowptr[i] + d_blocksum[blockIdx.x];
    d_rowptr[i] = rp;
    d_cursor[i] = rp;
    if (i == 0) d_rowptr[BN] = Eg;
}
__global__ void k_fill(const int* __restrict__ src, const int* __restrict__ dst){
    int e = blockIdx.x*blockDim.x + threadIdx.x;
    if (e >= Eg) return;
    int p = atomicAdd(&d_cursor[dst[e]], 1);
    d_csrsrc[p] = src[e];
}

// ------------------- normalized aggregation of raw x (warp/node, float4) -------------------
__global__ void k_aggx(const float* __restrict__ x, int oXagg){
    float* xagg = d_pool + oXagg;
    int node = (blockIdx.x*blockDim.x + threadIdx.x) >> 5;
    int lane = threadIdx.x & 31;
    if (node >= BN) return;
    float di = d_dinv1[node];
    int beg = d_rowptr[node], end = d_rowptr[node+1];
    float4 acc = make_float4(0.f,0.f,0.f,0.f);
    for (int e = beg; e < end; e++){
        int s = d_csrsrc[e];
        float c = d_dinv1[s] * di;
        float4 xv = *reinterpret_cast<const float4*>(&x[(size_t)s*128 + lane*4]);
        acc.x += xv.x*c; acc.y += xv.y*c; acc.z += xv.z*c; acc.w += xv.w*c;
    }
    float4 xs = *reinterpret_cast<const float4*>(&x[(size_t)node*128 + lane*4]);
    float sc = di*di;
    acc.x += xs.x*sc; acc.y += xs.y*sc; acc.z += xs.z*sc; acc.w += xs.w*sc;
    *reinterpret_cast<float4*>(&xagg[(size_t)node*128 + lane*4]) = acc;
}

// ------------------- GEMM 128x128 tile, 8x8/thread, conflict-free Ws cols -------------------
// Thread (tx,ty) computes rows ty*8..+7, cols {4tx..4tx+3, 64+4tx..64+4tx+3}.
__global__ __launch_bounds__(256) void k_gemm(int oX, const float* __restrict__ W,
                                              int oO, int M,
                                              const float* __restrict__ bias,
                                              int doRelu){
    const float* X = d_pool + oX;
    float* O = d_pool + oO;
    __shared__ float Xs[128][17];
    __shared__ float Ws[16][128];
    int tx = threadIdx.x & 15, ty = threadIdx.x >> 4;
    int row0 = blockIdx.x * 128;
    float acc[8][8];
    #pragma unroll
    for (int r = 0; r < 8; r++)
        #pragma unroll
        for (int c = 0; c < 8; c++) acc[r][c] = 0.f;
    for (int kb = 0; kb < 128; kb += 16){
        #pragma unroll
        for (int t = 0; t < 8; t++){
            int e = threadIdx.x + 256*t;
            int i = e >> 4, k = e & 15;
            Xs[i][k] = X[(size_t)(row0+i)*128 + kb + k];
        }
        #pragma unroll
        for (int t = 0; t < 8; t++){
            int e = threadIdx.x + 256*t;
            int kk = e >> 7, c = e & 127;
            Ws[kk][c] = W[(size_t)(kb+kk)*128 + c];
        }
        __syncthreads();
        #pragma unroll
        for (int kk = 0; kk < 16; kk++){
            float xr[8], wr[8];
            #pragma unroll
            for (int r = 0; r < 8; r++) xr[r] = Xs[ty*8+r][kk];
            float4 w0 = *reinterpret_cast<const float4*>(&Ws[kk][tx*4]);
            float4 w1 = *reinterpret_cast<const float4*>(&Ws[kk][64 + tx*4]);
            wr[0]=w0.x; wr[1]=w0.y; wr[2]=w0.z; wr[3]=w0.w;
            wr[4]=w1.x; wr[5]=w1.y; wr[6]=w1.z; wr[7]=w1.w;
            #pragma unroll
            for (int r = 0; r < 8; r++)
                #pragma unroll
                for (int c = 0; c < 8; c++)
                    acc[r][c] += xr[r]*wr[c];
        }
        __syncthreads();
    }
    float bv[8];
    #pragma unroll
    for (int c = 0; c < 4; c++) bv[c] = bias ? bias[tx*4 + c] : 0.f;
    #pragma unroll
    for (int c = 0; c < 4; c++) bv[4+c] = bias ? bias[64 + tx*4 + c] : 0.f;
    #pragma unroll
    for (int r = 0; r < 8; r++){
        float v[8];
        #pragma unroll
        for (int c = 0; c < 8; c++){
            float t = acc[r][c] + bv[c];
            v[c] = doRelu ? fmaxf(t, 0.f) : t;
        }
        float* orow = &O[(size_t)(row0+ty*8+r)*128];
        *reinterpret_cast<float4*>(orow + tx*4)      = make_float4(v[0],v[1],v[2],v[3]);
        *reinterpret_cast<float4*>(orow + 64 + tx*4) = make_float4(v[4],v[5],v[6],v[7]);
    }
}

// ------------------- info-score (edge, float4 gathers) -------------------
__global__ void k_info1(int oH){
    const float* h = d_pool + oH;
    int node = (blockIdx.x*blockDim.x + threadIdx.x) >> 5;
    int lane = threadIdx.x & 31;
    if (node >= BN) return;
    float di = d_dinv0[node];
    int beg = d_rowptr[node], end = d_rowptr[node+1];
    float4 acc = make_float4(0.f,0.f,0.f,0.f);
    for (int e = beg; e < end; e++){
        int s = d_csrsrc[e];
        float c = d_dinv0[s] * di;
        float4 hv = *reinterpret_cast<const float4*>(&h[(size_t)s*128 + lane*4]);
        acc.x += hv.x*c; acc.y += hv.y*c; acc.z += hv.z*c; acc.w += hv.w*c;
    }
    float4 hs = *reinterpret_cast<const float4*>(&h[(size_t)node*128 + lane*4]);
    float sum = fabsf(hs.x-acc.x) + fabsf(hs.y-acc.y) + fabsf(hs.z-acc.z) + fabsf(hs.w-acc.w);
    for (int o = 16; o > 0; o >>= 1) sum += __shfl_xor_sync(0xffffffffu, sum, o);
    if (lane == 0) d_score[node] = sum;
}

// ------------------- top-256-of-512 (bitonic, 256 threads x 2 elems) -------------------
__global__ void k_topk512(){
    __shared__ float v[512];
    __shared__ int   id[512];
    int g = blockIdx.x, t = threadIdx.x;
    v[t]       = d_score[g*512 + t];       id[t]       = t;
    v[t + 256] = d_score[g*512 + t + 256]; id[t + 256] = t + 256;
    __syncthreads();
    for (int k = 2; k <= 512; k <<= 1){
        for (int j = k >> 1; j > 0; j >>= 1){
            #pragma unroll
            for (int half = 0; half < 2; half++){
                int i = t + half*256;
                int ixj = i ^ j;
                if (ixj > i){
                    float va = v[i], vb = v[ixj]; int ia = id[i], ib = id[ixj];
                    bool aFirst = (va > vb) || (va == vb && ia < ib);
                    bool want = ((i & k) == 0);
                    if (aFirst != want){ v[i]=vb; v[ixj]=va; id[i]=ib; id[ixj]=ia; }
                }
            }
            __syncthreads();
        }
    }
    d_pos1[g*512 + t] = -1;
    d_pos1[g*512 + t + 256] = -1;
    __syncthreads();
    d_idx1[g*256 + t] = id[t];
    d_pos1[g*512 + id[t]] = t;
}

// ------------------- top-128-of-256 -------------------
__global__ void k_topk256(){
    __shared__ float v[256];
    __shared__ int   id[256];
    int g = blockIdx.x, t = threadIdx.x;
    v[t] = d_score[g*256 + t]; id[t] = t;
    __syncthreads();
    for (int k = 2; k <= 256; k <<= 1){
        for (int j = k >> 1; j > 0; j >>= 1){
            int ixj = t ^ j;
            if (ixj > t){
                float va = v[t], vb = v[ixj]; int ia = id[t], ib = id[ixj];
                bool aFirst = (va > vb) || (va == vb && ia < ib);
                bool want = ((t & k) == 0);
                if (aFirst != want){ v[t]=vb; v[ixj]=va; id[t]=ib; id[ixj]=ia; }
            }
            __syncthreads();
        }
    }
    if (t < 128) d_idx2[g*128 + t] = id[t];
}

// ------------------- gather kept rows + attention dot products -------------------
__global__ void k_gather(int oXin, int Nin, int K, int level,
                         const float* __restrict__ att, int oXout){
    const float* Xin = d_pool + oXin;
    float* Xout = d_pool + oXout;
    int gp = blockIdx.x;
    int g = gp / K;
    int node = g*Nin + (level == 1 ? d_idx1[gp] : d_idx2[gp]);
    int c = threadIdx.x; // 128
    float val = Xin[(size_t)node*128 + c];
    Xout[(size_t)gp*128 + c] = val;
    float qv = val*att[c], sv = val*att[128 + c];
    for (int o = 16; o > 0; o >>= 1){
        qv += __shfl_xor_sync(0xffffffffu, qv, o);
        sv += __shfl_xor_sync(0xffffffffu, sv, o);
    }
    __shared__ float smq[4], sms[4];
    int w = c >> 5, l = c & 31;
    if (l == 0){ smq[w] = qv; sms[w] = sv; }
    __syncthreads();
    if (c == 0){
        float q = smq[0]+smq[1]+smq[2]+smq[3];
        float s = sms[0]+sms[1]+sms[2]+sms[3];
        if (level == 1){ d_q1[gp] = q; d_s1v[gp] = s; }
        else           { d_q2[gp] = q; d_s2v[gp] = s; }
    }
}

// ------------------- build Ak from edge list via kept-position map -------------------
__global__ void k_buildAk(const int* __restrict__ src, const int* __restrict__ dst,
                          int oA1){
    float* A1 = d_pool + oA1;
    int e = blockIdx.x*blockDim.x + threadIdx.x;
    if (e >= Eg) return;
    int s = src[e], d = dst[e];
    int ps = d_pos1[s], pd = d_pos1[d];
    if (ps >= 0 && pd >= 0){
        int g = s >> 9;
        atomicAdd(&A1[((size_t)(g*Kp1) + ps)*Kp1 + pd], 1.0f);
    }
}

// ------------------- structure learning + fused rowsum->dinv (+ fused A1k gather at level 2) ----
// A_new = softmax(leaky(q_i+s_j)) + lamb*A_old;  rowsum(A_new) = 1 + lamb*rowsum(A_old)
//   dinvA = rsqrt(2 + rs_old), dinvB = rsqrt(1 + rs_old)
// level 2 reads A_old directly from A1 via idx2 (former k_gatherA2 fused away).
__global__ void k_struct(int level, int oSrc, int oDst, int K){
    const float* q = (level == 1) ? d_q1  : d_q2;
    const float* s = (level == 1) ? d_s1v : d_s2v;
    int row = blockIdx.x;
    int j = threadIdx.x;        // blockDim == K
    int g = row / K;
    float aold;
    if (level == 1){
        aold = d_pool[oSrc + (size_t)row*K + j];
    } else {
        int ip = d_idx2[row];
        int iq = d_idx2[g*K + j];
        aold = d_pool[oSrc + ((size_t)(g*Kp1) + ip)*Kp1 + iq];
    }
    float l = q[row] + s[g*K + j];
    l = l > 0.f ? l : NEG_SLOPE*l;
    __shared__ float redm[8], reds[8], redo[8];
    __shared__ float fmx, fsum;
    float m = l;
    for (int o = 16; o > 0; o >>= 1) m = fmaxf(m, __shfl_xor_sync(0xffffffffu, m, o));
    int w = j >> 5, lane = j & 31;
    if (lane == 0) redm[w] = m;
    __syncthreads();
    if (j == 0){
        float mm = redm[0];
        for (int w2 = 1; w2 < (K >> 5); w2++) mm = fmaxf(mm, redm[w2]);
        fmx = mm;
    }
    __syncthreads();
    float e = __expf(l - fmx);
    float su = e, so = aold;
    for (int o = 16; o > 0; o >>= 1){
        su += __shfl_xor_sync(0xffffffffu, su, o);
        so += __shfl_xor_sync(0xffffffffu, so, o);
    }
    if (lane == 0){ reds[w] = su; redo[w] = so; }
    __syncthreads();
    if (j == 0){
        float ss = reds[0], rs = redo[0];
        for (int w2 = 1; w2 < (K >> 5); w2++){ ss += reds[w2]; rs += redo[w2]; }
        fsum = ss;
        d_dinvA[row] = rsqrtf(2.0f + LAMBW*rs);
        d_dinvB[row] = rsqrtf(1.0f + LAMBW*rs);
    }
    __syncthreads();
    d_pool[oDst + (size_t)row*K + j] = e / fsum + LAMBW * aold;
}

// ------------------- readout (relu(max) || relu(mean)), optional accumulate -------------------
__global__ void k_readout(int oX, float* __restrict__ out, int K, int accumulate){
    const float* X = d_pool + oX;
    int g = blockIdx.x;
    int c = threadIdx.x;  // 128
    const float* Xg = X + (size_t)g*K*128;
    float mx = neg_inf(), sm = 0.f;
    #pragma unroll 8
    for (int p = 0; p < K; p++){
        float v = Xg[(size_t)p*128 + c];
        mx = fmaxf(mx, v); sm += v;
    }
    float o1 = fmaxf(mx, 0.f);
    float o2 = fmaxf(sm / (float)K, 0.f);
    if (accumulate){ out[g*256 + c] += o1; out[g*256 + 128 + c] += o2; }
    else           { out[g*256 + c]  = o1; out[g*256 + 128 + c]  = o2; }
}

// ------------------- batched dense GCN aggregation (64-row tiles, 8x4/thread) -------------------
// normal:    O[i][c] = act( uv[i]*( sum_j A[i][j]*uv[j]*X[j][c] + addSelf*uv[i]*X[i][c] ) + bias[c] )
// scoreMode: d_score[gi] = sum_c | X[i][c] - uv[i]*sum_j A[i][j]*uv[j]*X[j][c] |
__global__ __launch_bounds__(256) void k_dense_gcn(int oA, int oX, int uvsel,
        const float* __restrict__ bias, int oO, int M, int addSelf, int doRelu,
        int scoreMode){
    const float* A = d_pool + oA;
    const float* X = d_pool + oX;
    float* O = d_pool + oO;
    const float* uv = uvsel ? d_dinvB : d_dinvA;
    int tilesPer = M / 64;
    int g = blockIdx.x / tilesPer;
    int row0 = (blockIdx.x % tilesPer) * 64;
    __shared__ float As[64][32];
    __shared__ float Xs[32][128];
    int ty = threadIdx.x >> 5, tx = threadIdx.x & 31;
    float acc[8][4];
    #pragma unroll
    for (int r = 0; r < 8; r++){ acc[r][0]=acc[r][1]=acc[r][2]=acc[r][3]=0.f; }
    const float* Ag = A + (size_t)g*M*M;
    const float* Xg = X + (size_t)g*M*128;
    const float* vg = uv + g*M;
    for (int jb = 0; jb < M; jb += 32){
        #pragma unroll
        for (int t = 0; t < 2; t++){   // As: 64x32 = 2048 floats = 512 float4
            int e = threadIdx.x + 256*t; int r = e >> 3, j4 = e & 7;
            *reinterpret_cast<float4*>(&As[r][j4*4]) =
                *reinterpret_cast<const float4*>(&Ag[(size_t)(row0+r)*M + jb + j4*4]);
        }
        #pragma unroll
        for (int t = 0; t < 4; t++){   // Xs: 32x128 = 4096 floats = 1024 float4
            int e = threadIdx.x + 256*t; int jj = e >> 5, c4 = e & 31;
            float vj = vg[jb+jj];
            float4 xv = *reinterpret_cast<const float4*>(&Xg[(size_t)(jb+jj)*128 + c4*4]);
            xv.x *= vj; xv.y *= vj; xv.z *= vj; xv.w *= vj;
            *reinterpret_cast<float4*>(&Xs[jj][c4*4]) = xv;
        }
        __syncthreads();
        #pragma unroll
        for (int jj = 0; jj < 32; jj++){
            float4 xv = *reinterpret_cast<const float4*>(&Xs[jj][tx*4]);
            #pragma unroll
            for (int r = 0; r < 8; r++){
                float a = As[ty*8 + r][jj];
                acc[r][0] += a*xv.x; acc[r][1] += a*xv.y;
                acc[r][2] += a*xv.z; acc[r][3] += a*xv.w;
            }
        }
        __syncthreads();
    }
    if (scoreMode){
        #pragma unroll
        for (int r = 0; r < 8; r++){
            int i = row0 + ty*8 + r;
            int gi = g*M + i;
            float uu = vg[i];
            float p = 0.f;
            #pragma unroll
            for (int c4 = 0; c4 < 4; c4++){
                int c = tx*4 + c4;
                p += fabsf(Xg[(size_t)i*128 + c] - uu*acc[r][c4]);
            }
            for (int o = 16; o > 0; o >>= 1) p += __shfl_xor_sync(0xffffffffu, p, o);
            if (tx == 0) d_score[gi] = p;
        }
    } else {
        #pragma unroll
        for (int r = 0; r < 8; r++){
            int i = row0 + ty*8 + r;
            int gi = g*M + i;
            float uu = vg[i];
            #pragma unroll
            for (int c4 = 0; c4 < 4; c4++){
                int c = tx*4 + c4;
                float val = acc[r][c4];
                if (addSelf) val += uu * Xg[(size_t)i*128 + c];
                val *= uu;
                if (bias) val += bias[c];
                if (doRelu) val = fmaxf(val, 0.f);
                O[(size_t)gi*128 + c] = val;
            }
        }
    }
}

// ------------------- launch -------------------
extern "C" void kernel_launch(void* const* d_in, const int* in_sizes, int n_in,
                              void* d_out, int out_size){
    const float* x    = (const float*)d_in[0];
    const float* W1   = (const float*)d_in[1];
    const float* b1   = (const float*)d_in[2];
    const float* W2   = (const float*)d_in[3];
    const float* b2   = (const float*)d_in[4];
    const float* W3   = (const float*)d_in[5];
    const float* b3   = (const float*)d_in[6];
    const float* att1 = (const float*)d_in[7];
    const float* att2 = (const float*)d_in[8];
    const int* esrc   = (const int*)d_in[9];
    const int* edst   = (const int*)d_in[10];
    float* out = (float*)d_out;

    // ---- CSR build ----
    k_zero_deg<<<(BN + 255) / 256, 256>>>();
    k_degree<<<(Eg + 255) / 256, 256>>>(edst);
    k_scan1<<<BN / 256, 256>>>();          // also computes dinv1/dinv0
    k_scan2<<<1, 32>>>();
    k_scan3<<<BN / 256, 256>>>();
    k_fill<<<(Eg + 255) / 256, 256>>>(esrc, edst);

    // ---- conv1: xagg = norm-agg(x); h = relu(xagg@W1 + b1) IN-PLACE; info1 ----
    k_aggx<<<(BN * 32) / 256, 256>>>(x, OFF_XAGG);
    k_gemm<<<BN / 128, 256>>>(OFF_XAGG, W1, OFF_H, BN, b1, 1);
    k_info1<<<(BN * 32) / 256, 256>>>(OFF_H);

    // ---- pool1 ----
    k_topk512<<<Bg, 256>>>();
    k_gather<<<Bg * Kp1, 128>>>(OFF_H, Nn, Kp1, 1, att1, OFF_HK);
    k_zero_pool4<<<2048, 256>>>(OFF_A1, (Bg * Kp1 * Kp1) / 4);   // h dead -> A1
    k_buildAk<<<(Eg + 255) / 256, 256>>>(esrc, edst, OFF_A1);
    k_struct<<<Bg * Kp1, Kp1>>>(1, OFF_A1, OFF_A1, Kp1);          // + dinvA/dinvB
    k_readout<<<Bg, 128>>>(OFF_HK, out, Kp1, 0);

    // ---- conv2: hw = hk@W2 IN-PLACE; h2 = gcn(A1, hw) ----
    k_gemm<<<(Bg * Kp1) / 128, 256>>>(OFF_HK, W2, OFF_HW, Bg * Kp1, (const float*)0, 0);
    k_dense_gcn<<<Bg * (Kp1 / 64), 256>>>(OFF_A1, OFF_HW, 0, b2, OFF_H2, Kp1, 1, 1, 0);

    // ---- info2 (fused smooth+absdiff -> d_score) ----
    k_dense_gcn<<<Bg * (Kp1 / 64), 256>>>(OFF_A1, OFF_H2, 1, (const float*)0, OFF_HW, Kp1, 0, 0, 1);

    // ---- pool2 (gatherA2 fused into k_struct level 2) ----
    k_topk256<<<Bg, 256>>>();
    k_gather<<<Bg * Kp2, 128>>>(OFF_H2, Kp1, Kp2, 2, att2, OFF_H2K);
    k_struct<<<Bg * Kp2, Kp2>>>(2, OFF_A1, OFF_A2, Kp2);          // + dinvA for conv3
    k_readout<<<Bg, 128>>>(OFF_H2K, out, Kp2, 1);

    // ---- conv3: hw3 = h2k@W3 IN-PLACE; h3 = gcn(A2, hw3) ----
    k_gemm<<<(Bg * Kp2) / 128, 256>>>(OFF_H2K, W3, OFF_H2K, Bg * Kp2, (const float*)0, 0);
    k_dense_gcn<<<Bg * (Kp2 / 64), 256>>>(OFF_A2, OFF_H2K, 0, b3, OFF_H3, Kp2, 1, 1, 0);
    k_readout<<<Bg, 128>>>(OFF_H3, out, Kp2, 1);
}